// round 12
// baseline (speedup 1.0000x reference)
#include <cuda_runtime.h>
#include <cuda_fp16.h>
#include <math.h>
#include <stdint.h>

// Problem constants
#define BB 4
#define HH 64
#define WW 64
#define DD 256
#define NH 8
#define DK 32
#define DV 32
#define HW 4096
#define P2 1024
#define SPLIT 4
#define KSPS 1024        // keys per split

// Scratch
__device__ __half g_a16[BB * HW * DD];           //  8 MB blob f16
__device__ __half g_p16[BB * P2 * DD];           //  2 MB pooled blob f16
__device__ __half g_w16[3 * DD * DD];            // weights f16 [mode][n][k]
__device__ __half g_q[BB * NH * P2 * DK];        //  2 MB [bn][p][k] (pre-scaled 1/sqrt(K)*log2e)
__device__ __half g_k[BB * NH * HW * DK];        //  8 MB [bn][i][k]
__device__ __half g_v[BB * NH * DV * HW];        //  8 MB [bn][d][i] TRANSPOSED
__device__ float  g_po[SPLIT][BB * NH * P2 * DV];// 16 MB unnormalized partial O
__device__ float  g_pm[SPLIT][BB * NH * P2];     // partial max (log2 domain)
__device__ float  g_pl[SPLIT][BB * NH * P2];     // partial sum

#define ONES_F16X2 0x3C003C00u

// ---------------------------------------------------------------------------
__device__ __forceinline__ float ex2f(float x) {
    float r;
    asm("ex2.approx.ftz.f32 %0, %1;" : "=f"(r) : "f"(x));
    return r;
}
__device__ __forceinline__ uint32_t h2ex2(uint32_t x) {
    uint32_t r;
    asm("ex2.approx.f16x2 %0, %1;" : "=r"(r) : "r"(x));
    return r;
}
__device__ __forceinline__ void mma_f16(float& d0, float& d1, float& d2, float& d3,
                                        uint32_t a0, uint32_t a1, uint32_t a2, uint32_t a3,
                                        uint32_t b0, uint32_t b1) {
    asm volatile(
        "mma.sync.aligned.m16n8k16.row.col.f32.f16.f16.f32 "
        "{%0,%1,%2,%3}, {%4,%5,%6,%7}, {%8,%9}, {%0,%1,%2,%3};\n"
        : "+f"(d0), "+f"(d1), "+f"(d2), "+f"(d3)
        : "r"(a0), "r"(a1), "r"(a2), "r"(a3), "r"(b0), "r"(b1));
}
__device__ __forceinline__ void ldsm_x4(uint32_t& r0, uint32_t& r1, uint32_t& r2, uint32_t& r3,
                                        uint32_t a) {
    asm volatile("ldmatrix.sync.aligned.m8n8.x4.shared.b16 {%0,%1,%2,%3}, [%4];\n"
                 : "=r"(r0), "=r"(r1), "=r"(r2), "=r"(r3) : "r"(a));
}
__device__ __forceinline__ uint32_t smem_u32(const void* p) {
    return (uint32_t)__cvta_generic_to_shared(p);
}
__device__ __forceinline__ void cpa16(uint32_t s, const void* g) {
    asm volatile("cp.async.ca.shared.global [%0], [%1], 16;\n" :: "r"(s), "l"(g));
}
__device__ __forceinline__ void cpa_commit() { asm volatile("cp.async.commit_group;\n"); }
template <int N>
__device__ __forceinline__ void cpa_wait() { asm volatile("cp.async.wait_group %0;\n" :: "n"(N)); }

// ---------------------------------------------------------------------------
// Prep (merged): blk [0,512): blob f32->f16 + 2x2 maxpool.
//                blk [512,608): weights f32 [k][n] -> f16 [mode][n][k].
// ---------------------------------------------------------------------------
__global__ __launch_bounds__(256)
void prep_all(const float* __restrict__ blob,
              const float* __restrict__ wq, const float* __restrict__ wk,
              const float* __restrict__ wv)
{
    if (blockIdx.x < 512) {
        const int idx = blockIdx.x * 256 + threadIdx.x;    // 131072 total
        const int pp  = idx >> 5;
        const int c8  = (idx & 31) << 3;
        const int b  = pp >> 10, l = pp & 1023, h2 = l >> 5, w2 = l & 31;
        const int pix = (b * HH + 2 * h2) * WW + 2 * w2;
        const float* p = blob + (size_t)pix * DD + c8;

        float mx[8];
#pragma unroll
        for (int j = 0; j < 8; j++) mx[j] = -INFINITY;
        const int offs[4] = {0, DD, WW * DD, WW * DD + DD};
#pragma unroll
        for (int q = 0; q < 4; q++) {
            float4 v0 = *(const float4*)(p + offs[q]);
            float4 v1 = *(const float4*)(p + offs[q] + 4);
            float vv[8] = {v0.x, v0.y, v0.z, v0.w, v1.x, v1.y, v1.z, v1.w};
            __half hh[8];
#pragma unroll
            for (int j = 0; j < 8; j++) {
                hh[j] = __float2half_rn(vv[j]);
                mx[j] = fmaxf(mx[j], vv[j]);
            }
            const int pixq = pix + ((q >> 1) ? WW : 0) + (q & 1);
            *(uint4*)(g_a16 + (size_t)pixq * DD + c8) = *(uint4*)hh;
        }
        __half hm[8];
#pragma unroll
        for (int j = 0; j < 8; j++) hm[j] = __float2half_rn(mx[j]);
        *(uint4*)(g_p16 + (size_t)pp * DD + c8) = *(uint4*)hm;
    } else {
        const int idx = (blockIdx.x - 512) * 256 + threadIdx.x;   // 24576 total
        const int m   = idx >> 13;
        const int r   = idx & 8191;
        const int n   = r >> 5;
        const int k0  = (r & 31) << 3;
        const float* Wm = (m == 0) ? wq : (m == 1) ? wk : wv;
        __half tmp[8];
#pragma unroll
        for (int j = 0; j < 8; j++)
            tmp[j] = __float2half_rn(Wm[(size_t)(k0 + j) * DD + n]);
        *(uint4*)(g_w16 + ((size_t)m * DD + n) * DD + k0) = *(uint4*)tmp;
    }
}

// ---------------------------------------------------------------------------
// f16 tensor-core projections: 576 blocks (unchanged).
// ---------------------------------------------------------------------------
__global__ __launch_bounds__(256, 2)
void proj_gemm(const float* __restrict__ bq, const float* __restrict__ bk,
               const float* __restrict__ bv)
{
    __shared__ __half As[2][128][40];
    __shared__ __half Ws[2][128][40];

    const int tid  = threadIdx.x;
    const int w    = tid >> 5;
    const int lane = tid & 31;
    const int g    = lane >> 2;
    const int tig  = lane & 3;
    const int rsel = lane & 7;
    const int quad = lane >> 3;
    const int mw   = w & 3;
    const int nw   = w >> 2;

    const int blk = blockIdx.x;
    int mode, mt, n0;
    if (blk < 64)       { mode = 0; mt = blk >> 1;          n0 = (blk & 1) << 7; }
    else if (blk < 320) { mode = 1; mt = (blk - 64) >> 1;   n0 = (blk & 1) << 7; }
    else                { mode = 2; mt = (blk - 320) >> 1;  n0 = (blk & 1) << 7; }
    const int m0 = mt << 7;

    const __half* Aptr = (mode == 0) ? g_p16 : g_a16;
    const __half* Wptr = g_w16 + (size_t)mode * DD * DD;
    const float*  bias = (mode == 0) ? bq : (mode == 1) ? bk : bv;

    auto stage = [&](int k0, int buf) {
#pragma unroll
        for (int t = 0; t < 2; t++) {
            const int i   = tid + 256 * t;
            const int row = i >> 2;
            const int c   = i & 3;
            cpa16(smem_u32(&As[buf][row][c * 8]), Aptr + (size_t)(m0 + row) * DD + k0 + c * 8);
            cpa16(smem_u32(&Ws[buf][row][c * 8]), Wptr + (size_t)(n0 + row) * DD + k0 + c * 8);
        }
    };

    float acc[2][8][4];
#pragma unroll
    for (int t = 0; t < 2; t++)
#pragma unroll
        for (int nt = 0; nt < 8; nt++)
#pragma unroll
            for (int j = 0; j < 4; j++) acc[t][nt][j] = 0.0f;

    stage(0, 0);
    cpa_commit();

    for (int ks = 0; ks < 8; ks++) {
        const int buf = ks & 1;
        if (ks + 1 < 8) {
            stage((ks + 1) * 32, buf ^ 1);
            cpa_commit();
            cpa_wait<1>();
        } else {
            cpa_wait<0>();
        }
        __syncthreads();

#pragma unroll
        for (int kc = 0; kc < 2; kc++) {
            uint32_t af[2][4];
#pragma unroll
            for (int t = 0; t < 2; t++) {
                const uint32_t addr = smem_u32(
                    &As[buf][mw * 32 + t * 16 + rsel + ((quad & 1) << 3)]
                            [kc * 16 + ((quad >> 1) << 3)]);
                ldsm_x4(af[t][0], af[t][1], af[t][2], af[t][3], addr);
            }
#pragma unroll
            for (int p = 0; p < 4; p++) {
                uint32_t b0, b1, b2, b3;
                const uint32_t addr = smem_u32(
                    &Ws[buf][nw * 64 + p * 16 + rsel + ((quad >> 1) << 3)]
                            [kc * 16 + ((quad & 1) << 3)]);
                ldsm_x4(b0, b1, b2, b3, addr);
#pragma unroll
                for (int t = 0; t < 2; t++) {
                    mma_f16(acc[t][2 * p][0], acc[t][2 * p][1], acc[t][2 * p][2], acc[t][2 * p][3],
                            af[t][0], af[t][1], af[t][2], af[t][3], b0, b1);
                    mma_f16(acc[t][2 * p + 1][0], acc[t][2 * p + 1][1], acc[t][2 * p + 1][2], acc[t][2 * p + 1][3],
                            af[t][0], af[t][1], af[t][2], af[t][3], b2, b3);
                }
            }
        }
        __syncthreads();
    }

    const float QSCL = 0.17677669529663687f * 1.4426950408889634f;
#pragma unroll
    for (int t = 0; t < 2; t++) {
#pragma unroll
        for (int nt = 0; nt < 8; nt++) {
#pragma unroll
            for (int half = 0; half < 2; half++) {
                const int r = m0 + mw * 32 + t * 16 + g + half * 8;
#pragma unroll
                for (int j = 0; j < 2; j++) {
                    const int c = n0 + nw * 64 + nt * 8 + 2 * tig + j;
                    float val   = acc[t][nt][half * 2 + j] + __ldg(bias + c);
                    const int n = c >> 5;
                    const int d = c & 31;
                    if (mode == 0) {
                        val *= QSCL;
                        const int b = r >> 10, p2 = r & 1023;
                        g_q[(((b * NH + n) * P2) + p2) * DK + d] = __float2half_rn(val);
                    } else if (mode == 1) {
                        const int b = r >> 12, ii = r & 4095;
                        g_k[(((b * NH + n) * HW) + ii) * DK + d] = __float2half_rn(val);
                    } else {
                        val = val / (1.0f + __expf(-val));
                        const int b = r >> 12, ii = r & 4095;
                        g_v[(((size_t)(b * NH + n) * DV) + d) * HW + ii] = __float2half_rn(val);
                    }
                }
            }
        }
    }
}

// ---------------------------------------------------------------------------
// Split-K fp16 flash attention (SPLIT=4 -> 1024 blocks, 16 tiles each).
// Block: 8 warps / 256 thr / 128 queries; 1024 keys; 64-key tiles.
// 3-stage cp.async pipeline (one barrier per tile); warp-uniform lazy max;
// row-sum l via ones-fragment MMA.
// ---------------------------------------------------------------------------
__global__ __launch_bounds__(256)
void attn_tc_kernel()
{
    __shared__ __half Qs[128][40];
    __shared__ __half Ks[3][64][40];
    __shared__ __half VsT[3][32][72];

    const int tid  = threadIdx.x;
    const int w    = tid >> 5;            // 0..7
    const int lane = tid & 31;
    const int g    = lane >> 2;
    const int tig  = lane & 3;
    const int rsel = lane & 7;
    const int quad = lane >> 3;

    const int qt = blockIdx.x;            // 0..7 (128 queries each)
    const int n  = blockIdx.y;
    const int z  = blockIdx.z;            // 0..15
    const int b  = z >> 2;
    const int s  = z & 3;                 // key split 0..3
    const int bn = b * NH + n;

    const __half* qglob = g_q + (size_t)(bn * P2 + qt * 128) * DK;
    const __half* kglob = g_k + ((size_t)bn * HW + s * KSPS) * DK;
    const __half* vglob = g_v + (size_t)bn * DV * HW + s * KSPS;

    // stage Q once: 128 rows x 64B = 512 x 16B
#pragma unroll
    for (int t = 0; t < 2; t++) {
        const int i   = tid + 256 * t;
        const int row = i >> 2;
        const int c   = i & 3;
        *(float4*)&Qs[row][c * 8] = *(const float4*)(qglob + row * DK + c * 8);
    }

    auto stage = [&](int j0, int buf) {
        {   // K: 64 rows x 64B = 256 chunks
            const int row = tid >> 2;
            const int c   = tid & 3;
            cpa16(smem_u32(&Ks[buf][row][c * 8]), kglob + (size_t)(j0 + row) * DK + c * 8);
        }
        {   // V^T: 32 rows x 128B = 256 chunks
            const int row = tid >> 3;
            const int c   = tid & 7;
            cpa16(smem_u32(&VsT[buf][row][c * 8]), vglob + (size_t)row * HW + j0 + c * 8);
        }
    };

    const int NT = KSPS / 64;             // 16
    stage(0, 0);   cpa_commit();
    stage(64, 1);  cpa_commit();
    __syncthreads();                      // Qs visible

    uint32_t Qf[2][4];
    const int r0 = w * 16 + g;
#pragma unroll
    for (int kc = 0; kc < 2; kc++) {
        Qf[kc][0] = *(const uint32_t*)&Qs[r0    ][kc * 16 + 2 * tig    ];
        Qf[kc][1] = *(const uint32_t*)&Qs[r0 + 8][kc * 16 + 2 * tig    ];
        Qf[kc][2] = *(const uint32_t*)&Qs[r0    ][kc * 16 + 2 * tig + 8];
        Qf[kc][3] = *(const uint32_t*)&Qs[r0 + 8][kc * 16 + 2 * tig + 8];
    }

    float m = -INFINITY;                  // warp-uniform running max (log2 domain)
    float lacc[4] = {0.0f, 0.0f, 0.0f, 0.0f};
    float oacc[4][4];
#pragma unroll
    for (int i = 0; i < 4; i++)
#pragma unroll
        for (int j = 0; j < 4; j++) oacc[i][j] = 0.0f;

    for (int it = 0; it < NT; it++) {
        const int buf = it % 3;
        if (it == NT - 1) cpa_wait<0>(); else cpa_wait<1>();
        __syncthreads();                  // one barrier per tile

        // ---- S = Q K^T ----
        float sacc[8][4];
#pragma unroll
        for (int nt = 0; nt < 8; nt++)
#pragma unroll
            for (int j = 0; j < 4; j++) sacc[nt][j] = 0.0f;

#pragma unroll
        for (int kc = 0; kc < 2; kc++) {
#pragma unroll
            for (int p = 0; p < 4; p++) {
                uint32_t b0, b1, b2, b3;
                const uint32_t addr = smem_u32(
                    &Ks[buf][p * 16 + rsel + ((quad >> 1) << 3)]
                            [kc * 16 + ((quad & 1) << 3)]);
                ldsm_x4(b0, b1, b2, b3, addr);
                mma_f16(sacc[2 * p][0], sacc[2 * p][1], sacc[2 * p][2], sacc[2 * p][3],
                        Qf[kc][0], Qf[kc][1], Qf[kc][2], Qf[kc][3], b0, b1);
                mma_f16(sacc[2 * p + 1][0], sacc[2 * p + 1][1], sacc[2 * p + 1][2], sacc[2 * p + 1][3],
                        Qf[kc][0], Qf[kc][1], Qf[kc][2], Qf[kc][3], b2, b3);
            }
        }

        // ---- warp-uniform lazy max ----
        float mx = -INFINITY;
#pragma unroll
        for (int nt = 0; nt < 8; nt++) {
            mx = fmaxf(mx, fmaxf(fmaxf(sacc[nt][0], sacc[nt][1]),
                                 fmaxf(sacc[nt][2], sacc[nt][3])));
        }
#pragma unroll
        for (int d = 16; d >= 1; d >>= 1)
            mx = fmaxf(mx, __shfl_xor_sync(0xffffffffu, mx, d));

        if (mx > m) {                     // warp-uniform branch; rare after warmup
            const float sc = ex2f(m - mx);   // 0 on first tile
            m = mx;
#pragma unroll
            for (int nt = 0; nt < 4; nt++) {
                oacc[nt][0] *= sc; oacc[nt][1] *= sc;
                oacc[nt][2] *= sc; oacc[nt][3] *= sc;
            }
            lacc[0] *= sc; lacc[1] *= sc; lacc[2] *= sc; lacc[3] *= sc;
        }

        // ---- P = 2^(S - m) in f16 ----
        uint32_t hlo[8], hhi[8];
#pragma unroll
        for (int nt = 0; nt < 8; nt++) {
            __half2 d0 = __floats2half2_rn(sacc[nt][0] - m, sacc[nt][1] - m);
            __half2 d1 = __floats2half2_rn(sacc[nt][2] - m, sacc[nt][3] - m);
            hlo[nt] = h2ex2(*(uint32_t*)&d0);
            hhi[nt] = h2ex2(*(uint32_t*)&d1);
        }

        // ---- O += P V ; l += P @ 1 ----
#pragma unroll
        for (int kc = 0; kc < 4; kc++) {
            const uint32_t a0 = hlo[2 * kc];
            const uint32_t a1 = hhi[2 * kc];
            const uint32_t a2 = hlo[2 * kc + 1];
            const uint32_t a3 = hhi[2 * kc + 1];
            mma_f16(lacc[0], lacc[1], lacc[2], lacc[3],
                    a0, a1, a2, a3, ONES_F16X2, ONES_F16X2);
#pragma unroll
            for (int p = 0; p < 2; p++) {
                uint32_t b0, b1, b2, b3;
                const uint32_t addr = smem_u32(
                    &VsT[buf][p * 16 + rsel + ((quad >> 1) << 3)]
                             [kc * 16 + ((quad & 1) << 3)]);
                ldsm_x4(b0, b1, b2, b3, addr);
                mma_f16(oacc[2 * p][0], oacc[2 * p][1], oacc[2 * p][2], oacc[2 * p][3],
                        a0, a1, a2, a3, b0, b1);
                mma_f16(oacc[2 * p + 1][0], oacc[2 * p + 1][1], oacc[2 * p + 1][2], oacc[2 * p + 1][3],
                        a0, a1, a2, a3, b2, b3);
            }
        }

        // stage tile it+2 into buffer (it+2)%3
        if (it + 2 < NT) {
            stage((it + 2) * 64, (it + 2) % 3);
            cpa_commit();
        }
    }

    // ---- write partials (unnormalized) ----
    const int q0   = qt * 128 + w * 16 + g;
    const int row0 = bn * P2 + q0;
    const int row1 = row0 + 8;
    if (tig == 0) {
        g_pm[s][row0] = m;   g_pl[s][row0] = lacc[0];
        g_pm[s][row1] = m;   g_pl[s][row1] = lacc[2];
    }
    float* po0 = &g_po[s][(size_t)row0 * DV];
    float* po1 = &g_po[s][(size_t)row1 * DV];
#pragma unroll
    for (int nt = 0; nt < 4; nt++) {
        *(float2*)(po0 + nt * 8 + 2 * tig) = make_float2(oacc[nt][0], oacc[nt][1]);
        *(float2*)(po1 + nt * 8 + 2 * tig) = make_float2(oacc[nt][2], oacc[nt][3]);
    }
}

// ---------------------------------------------------------------------------
// Combine the four key-splits and normalize (8 elems/thread, float4).
// ---------------------------------------------------------------------------
__global__ __launch_bounds__(256)
void combine_kernel(float* __restrict__ out)
{
    const int idx = blockIdx.x * 256 + threadIdx.x;    // 131072 total
    const int row = idx >> 2;                          // bn*P2 + p
    const int d0  = (idx & 3) << 3;

    float pm[SPLIT];
#pragma unroll
    for (int s = 0; s < SPLIT; s++) pm[s] = g_pm[s][row];
    float M = pm[0];
#pragma unroll
    for (int s = 1; s < SPLIT; s++) M = fmaxf(M, pm[s]);

    float wgt[SPLIT];
    float den = 0.0f;
#pragma unroll
    for (int s = 0; s < SPLIT; s++) {
        wgt[s] = ex2f(pm[s] - M);
        den += g_pl[s][row] * wgt[s];
    }
    const float inv = 1.0f / den;
#pragma unroll
    for (int s = 0; s < SPLIT; s++) wgt[s] *= inv;

    const int b = row >> 13;
    const int n = (row >> 10) & 7;
    const int p = row & 1023;
    float4* o = (float4*)(out + ((size_t)(b * P2 + p) * 256) + n * DV + d0);

#pragma unroll
    for (int t = 0; t < 2; t++) {
        float4 r = make_float4(0.0f, 0.0f, 0.0f, 0.0f);
#pragma unroll
        for (int s = 0; s < SPLIT; s++) {
            float4 x = *(const float4*)&g_po[s][(size_t)row * DV + d0 + 4 * t];
            r.x += x.x * wgt[s];
            r.y += x.y * wgt[s];
            r.z += x.z * wgt[s];
            r.w += x.w * wgt[s];
        }
        o[t] = r;
    }
}

// ---------------------------------------------------------------------------
extern "C" void kernel_launch(void* const* d_in, const int* in_sizes, int n_in,
                              void* d_out, int out_size)
{
    const float* blob = (const float*)d_in[0];
    const float* wq   = (const float*)d_in[1];
    const float* bq   = (const float*)d_in[2];
    const float* wk   = (const float*)d_in[3];
    const float* bk   = (const float*)d_in[4];
    const float* wv   = (const float*)d_in[5];
    const float* bv   = (const float*)d_in[6];
    float* out        = (float*)d_out;

    prep_all<<<608, 256>>>(blob, wq, wk, wv);
    proj_gemm<<<576, 256>>>(bq, bk, bv);
    attn_tc_kernel<<<dim3(8, NH, BB * SPLIT), 256>>>();
    combine_kernel<<<512, 256>>>(out);
}

// round 13
// speedup vs baseline: 1.0174x; 1.0174x over previous
#include <cuda_runtime.h>
#include <cuda_fp16.h>
#include <math.h>
#include <stdint.h>

// Problem constants
#define BB 4
#define HH 64
#define WW 64
#define DD 256
#define NH 8
#define DK 32
#define DV 32
#define HW 4096
#define P2 1024
#define SPLIT 4
#define KSPS 1024        // keys per split

// Scratch
__device__ __half g_a16[BB * HW * DD];           //  8 MB blob f16
__device__ __half g_p16[BB * P2 * DD];           //  2 MB pooled blob f16
__device__ __half g_w16[3 * DD * DD];            // weights f16 [mode][n][k]
__device__ __half g_q[BB * NH * P2 * DK];        //  2 MB [bn][p][k] (pre-scaled 1/sqrt(K)*log2e)
__device__ __half g_k[BB * NH * HW * DK];        //  8 MB [bn][i][k]
__device__ __half g_v[BB * NH * DV * HW];        //  8 MB [bn][d][i] TRANSPOSED
__device__ float  g_po[SPLIT][BB * NH * P2 * DV];// 16 MB unnormalized partial O
__device__ float  g_pm[SPLIT][BB * NH * P2];     // partial max (log2 domain)
__device__ float  g_pl[SPLIT][BB * NH * P2];     // partial sum

#define ONES_F16X2 0x3C003C00u

// ---------------------------------------------------------------------------
__device__ __forceinline__ float ex2f(float x) {
    float r;
    asm("ex2.approx.ftz.f32 %0, %1;" : "=f"(r) : "f"(x));
    return r;
}
__device__ __forceinline__ uint32_t h2ex2(uint32_t x) {
    uint32_t r;
    asm("ex2.approx.f16x2 %0, %1;" : "=r"(r) : "r"(x));
    return r;
}
__device__ __forceinline__ void mma_f16(float& d0, float& d1, float& d2, float& d3,
                                        uint32_t a0, uint32_t a1, uint32_t a2, uint32_t a3,
                                        uint32_t b0, uint32_t b1) {
    asm volatile(
        "mma.sync.aligned.m16n8k16.row.col.f32.f16.f16.f32 "
        "{%0,%1,%2,%3}, {%4,%5,%6,%7}, {%8,%9}, {%0,%1,%2,%3};\n"
        : "+f"(d0), "+f"(d1), "+f"(d2), "+f"(d3)
        : "r"(a0), "r"(a1), "r"(a2), "r"(a3), "r"(b0), "r"(b1));
}
__device__ __forceinline__ void ldsm_x4(uint32_t& r0, uint32_t& r1, uint32_t& r2, uint32_t& r3,
                                        uint32_t a) {
    asm volatile("ldmatrix.sync.aligned.m8n8.x4.shared.b16 {%0,%1,%2,%3}, [%4];\n"
                 : "=r"(r0), "=r"(r1), "=r"(r2), "=r"(r3) : "r"(a));
}
__device__ __forceinline__ uint32_t smem_u32(const void* p) {
    return (uint32_t)__cvta_generic_to_shared(p);
}
__device__ __forceinline__ void cpa16(uint32_t s, const void* g) {
    asm volatile("cp.async.ca.shared.global [%0], [%1], 16;\n" :: "r"(s), "l"(g));
}
__device__ __forceinline__ void cpa_commit() { asm volatile("cp.async.commit_group;\n"); }
template <int N>
__device__ __forceinline__ void cpa_wait() { asm volatile("cp.async.wait_group %0;\n" :: "n"(N)); }

// ---------------------------------------------------------------------------
// Prep (merged): blk [0,512): blob f32->f16 + 2x2 maxpool.
//                blk [512,608): weights f32 [k][n] -> f16 [mode][n][k].
// ---------------------------------------------------------------------------
__global__ __launch_bounds__(256)
void prep_all(const float* __restrict__ blob,
              const float* __restrict__ wq, const float* __restrict__ wk,
              const float* __restrict__ wv)
{
    if (blockIdx.x < 512) {
        const int idx = blockIdx.x * 256 + threadIdx.x;    // 131072 total
        const int pp  = idx >> 5;
        const int c8  = (idx & 31) << 3;
        const int b  = pp >> 10, l = pp & 1023, h2 = l >> 5, w2 = l & 31;
        const int pix = (b * HH + 2 * h2) * WW + 2 * w2;
        const float* p = blob + (size_t)pix * DD + c8;

        float mx[8];
#pragma unroll
        for (int j = 0; j < 8; j++) mx[j] = -INFINITY;
        const int offs[4] = {0, DD, WW * DD, WW * DD + DD};
#pragma unroll
        for (int q = 0; q < 4; q++) {
            float4 v0 = *(const float4*)(p + offs[q]);
            float4 v1 = *(const float4*)(p + offs[q] + 4);
            float vv[8] = {v0.x, v0.y, v0.z, v0.w, v1.x, v1.y, v1.z, v1.w};
            __half hh[8];
#pragma unroll
            for (int j = 0; j < 8; j++) {
                hh[j] = __float2half_rn(vv[j]);
                mx[j] = fmaxf(mx[j], vv[j]);
            }
            const int pixq = pix + ((q >> 1) ? WW : 0) + (q & 1);
            *(uint4*)(g_a16 + (size_t)pixq * DD + c8) = *(uint4*)hh;
        }
        __half hm[8];
#pragma unroll
        for (int j = 0; j < 8; j++) hm[j] = __float2half_rn(mx[j]);
        *(uint4*)(g_p16 + (size_t)pp * DD + c8) = *(uint4*)hm;
    } else {
        const int idx = (blockIdx.x - 512) * 256 + threadIdx.x;   // 24576 total
        const int m   = idx >> 13;
        const int r   = idx & 8191;
        const int n   = r >> 5;
        const int k0  = (r & 31) << 3;
        const float* Wm = (m == 0) ? wq : (m == 1) ? wk : wv;
        __half tmp[8];
#pragma unroll
        for (int j = 0; j < 8; j++)
            tmp[j] = __float2half_rn(Wm[(size_t)(k0 + j) * DD + n]);
        *(uint4*)(g_w16 + ((size_t)m * DD + n) * DD + k0) = *(uint4*)tmp;
    }
}

// ---------------------------------------------------------------------------
// f16 tensor-core projections: 576 blocks (unchanged).
// ---------------------------------------------------------------------------
__global__ __launch_bounds__(256, 2)
void proj_gemm(const float* __restrict__ bq, const float* __restrict__ bk,
               const float* __restrict__ bv)
{
    __shared__ __half As[2][128][40];
    __shared__ __half Ws[2][128][40];

    const int tid  = threadIdx.x;
    const int w    = tid >> 5;
    const int lane = tid & 31;
    const int g    = lane >> 2;
    const int tig  = lane & 3;
    const int rsel = lane & 7;
    const int quad = lane >> 3;
    const int mw   = w & 3;
    const int nw   = w >> 2;

    const int blk = blockIdx.x;
    int mode, mt, n0;
    if (blk < 64)       { mode = 0; mt = blk >> 1;          n0 = (blk & 1) << 7; }
    else if (blk < 320) { mode = 1; mt = (blk - 64) >> 1;   n0 = (blk & 1) << 7; }
    else                { mode = 2; mt = (blk - 320) >> 1;  n0 = (blk & 1) << 7; }
    const int m0 = mt << 7;

    const __half* Aptr = (mode == 0) ? g_p16 : g_a16;
    const __half* Wptr = g_w16 + (size_t)mode * DD * DD;
    const float*  bias = (mode == 0) ? bq : (mode == 1) ? bk : bv;

    auto stage = [&](int k0, int buf) {
#pragma unroll
        for (int t = 0; t < 2; t++) {
            const int i   = tid + 256 * t;
            const int row = i >> 2;
            const int c   = i & 3;
            cpa16(smem_u32(&As[buf][row][c * 8]), Aptr + (size_t)(m0 + row) * DD + k0 + c * 8);
            cpa16(smem_u32(&Ws[buf][row][c * 8]), Wptr + (size_t)(n0 + row) * DD + k0 + c * 8);
        }
    };

    float acc[2][8][4];
#pragma unroll
    for (int t = 0; t < 2; t++)
#pragma unroll
        for (int nt = 0; nt < 8; nt++)
#pragma unroll
            for (int j = 0; j < 4; j++) acc[t][nt][j] = 0.0f;

    stage(0, 0);
    cpa_commit();

    for (int ks = 0; ks < 8; ks++) {
        const int buf = ks & 1;
        if (ks + 1 < 8) {
            stage((ks + 1) * 32, buf ^ 1);
            cpa_commit();
            cpa_wait<1>();
        } else {
            cpa_wait<0>();
        }
        __syncthreads();

#pragma unroll
        for (int kc = 0; kc < 2; kc++) {
            uint32_t af[2][4];
#pragma unroll
            for (int t = 0; t < 2; t++) {
                const uint32_t addr = smem_u32(
                    &As[buf][mw * 32 + t * 16 + rsel + ((quad & 1) << 3)]
                            [kc * 16 + ((quad >> 1) << 3)]);
                ldsm_x4(af[t][0], af[t][1], af[t][2], af[t][3], addr);
            }
#pragma unroll
            for (int p = 0; p < 4; p++) {
                uint32_t b0, b1, b2, b3;
                const uint32_t addr = smem_u32(
                    &Ws[buf][nw * 64 + p * 16 + rsel + ((quad >> 1) << 3)]
                            [kc * 16 + ((quad & 1) << 3)]);
                ldsm_x4(b0, b1, b2, b3, addr);
#pragma unroll
                for (int t = 0; t < 2; t++) {
                    mma_f16(acc[t][2 * p][0], acc[t][2 * p][1], acc[t][2 * p][2], acc[t][2 * p][3],
                            af[t][0], af[t][1], af[t][2], af[t][3], b0, b1);
                    mma_f16(acc[t][2 * p + 1][0], acc[t][2 * p + 1][1], acc[t][2 * p + 1][2], acc[t][2 * p + 1][3],
                            af[t][0], af[t][1], af[t][2], af[t][3], b2, b3);
                }
            }
        }
        __syncthreads();
    }

    const float QSCL = 0.17677669529663687f * 1.4426950408889634f;
#pragma unroll
    for (int t = 0; t < 2; t++) {
#pragma unroll
        for (int nt = 0; nt < 8; nt++) {
#pragma unroll
            for (int half = 0; half < 2; half++) {
                const int r = m0 + mw * 32 + t * 16 + g + half * 8;
#pragma unroll
                for (int j = 0; j < 2; j++) {
                    const int c = n0 + nw * 64 + nt * 8 + 2 * tig + j;
                    float val   = acc[t][nt][half * 2 + j] + __ldg(bias + c);
                    const int n = c >> 5;
                    const int d = c & 31;
                    if (mode == 0) {
                        val *= QSCL;
                        const int b = r >> 10, p2 = r & 1023;
                        g_q[(((b * NH + n) * P2) + p2) * DK + d] = __float2half_rn(val);
                    } else if (mode == 1) {
                        const int b = r >> 12, ii = r & 4095;
                        g_k[(((b * NH + n) * HW) + ii) * DK + d] = __float2half_rn(val);
                    } else {
                        val = val / (1.0f + __expf(-val));
                        const int b = r >> 12, ii = r & 4095;
                        g_v[(((size_t)(b * NH + n) * DV) + d) * HW + ii] = __float2half_rn(val);
                    }
                }
            }
        }
    }
}

// ---------------------------------------------------------------------------
// Split-K fp16 flash attention (SPLIT=4 -> 1024 blocks, 16 tiles each).
// Block: 8 warps / 256 thr / 128 queries; 1024 keys; 64-key tiles.
// 3-stage cp.async pipeline (one barrier per tile); warp-uniform lazy max;
// row-sum l via ones-fragment MMA.
// ---------------------------------------------------------------------------
__global__ __launch_bounds__(256)
void attn_tc_kernel()
{
    __shared__ __half Qs[128][40];
    __shared__ __half Ks[3][64][40];
    __shared__ __half VsT[3][32][72];

    const int tid  = threadIdx.x;
    const int w    = tid >> 5;            // 0..7
    const int lane = tid & 31;
    const int g    = lane >> 2;
    const int tig  = lane & 3;
    const int rsel = lane & 7;
    const int quad = lane >> 3;

    const int qt = blockIdx.x;            // 0..7 (128 queries each)
    const int n  = blockIdx.y;
    const int z  = blockIdx.z;            // 0..15
    const int b  = z >> 2;
    const int s  = z & 3;                 // key split 0..3
    const int bn = b * NH + n;

    const __half* qglob = g_q + (size_t)(bn * P2 + qt * 128) * DK;
    const __half* kglob = g_k + ((size_t)bn * HW + s * KSPS) * DK;
    const __half* vglob = g_v + (size_t)bn * DV * HW + s * KSPS;

    // stage Q once: 128 rows x 64B = 512 x 16B
#pragma unroll
    for (int t = 0; t < 2; t++) {
        const int i   = tid + 256 * t;
        const int row = i >> 2;
        const int c   = i & 3;
        *(float4*)&Qs[row][c * 8] = *(const float4*)(qglob + row * DK + c * 8);
    }

    auto stage = [&](int j0, int buf) {
        {   // K: 64 rows x 64B = 256 chunks
            const int row = tid >> 2;
            const int c   = tid & 3;
            cpa16(smem_u32(&Ks[buf][row][c * 8]), kglob + (size_t)(j0 + row) * DK + c * 8);
        }
        {   // V^T: 32 rows x 128B = 256 chunks
            const int row = tid >> 3;
            const int c   = tid & 7;
            cpa16(smem_u32(&VsT[buf][row][c * 8]), vglob + (size_t)row * HW + j0 + c * 8);
        }
    };

    const int NT = KSPS / 64;             // 16
    stage(0, 0);   cpa_commit();
    stage(64, 1);  cpa_commit();
    __syncthreads();                      // Qs visible

    uint32_t Qf[2][4];
    const int r0 = w * 16 + g;
#pragma unroll
    for (int kc = 0; kc < 2; kc++) {
        Qf[kc][0] = *(const uint32_t*)&Qs[r0    ][kc * 16 + 2 * tig    ];
        Qf[kc][1] = *(const uint32_t*)&Qs[r0 + 8][kc * 16 + 2 * tig    ];
        Qf[kc][2] = *(const uint32_t*)&Qs[r0    ][kc * 16 + 2 * tig + 8];
        Qf[kc][3] = *(const uint32_t*)&Qs[r0 + 8][kc * 16 + 2 * tig + 8];
    }

    float m = -INFINITY;                  // warp-uniform running max (log2 domain)
    float lacc[4] = {0.0f, 0.0f, 0.0f, 0.0f};
    float oacc[4][4];
#pragma unroll
    for (int i = 0; i < 4; i++)
#pragma unroll
        for (int j = 0; j < 4; j++) oacc[i][j] = 0.0f;

    for (int it = 0; it < NT; it++) {
        const int buf = it % 3;
        if (it == NT - 1) cpa_wait<0>(); else cpa_wait<1>();
        __syncthreads();                  // one barrier per tile

        // ---- S = Q K^T ----
        float sacc[8][4];
#pragma unroll
        for (int nt = 0; nt < 8; nt++)
#pragma unroll
            for (int j = 0; j < 4; j++) sacc[nt][j] = 0.0f;

#pragma unroll
        for (int kc = 0; kc < 2; kc++) {
#pragma unroll
            for (int p = 0; p < 4; p++) {
                uint32_t b0, b1, b2, b3;
                const uint32_t addr = smem_u32(
                    &Ks[buf][p * 16 + rsel + ((quad >> 1) << 3)]
                            [kc * 16 + ((quad & 1) << 3)]);
                ldsm_x4(b0, b1, b2, b3, addr);
                mma_f16(sacc[2 * p][0], sacc[2 * p][1], sacc[2 * p][2], sacc[2 * p][3],
                        Qf[kc][0], Qf[kc][1], Qf[kc][2], Qf[kc][3], b0, b1);
                mma_f16(sacc[2 * p + 1][0], sacc[2 * p + 1][1], sacc[2 * p + 1][2], sacc[2 * p + 1][3],
                        Qf[kc][0], Qf[kc][1], Qf[kc][2], Qf[kc][3], b2, b3);
            }
        }

        // ---- warp-uniform lazy max ----
        float mx = -INFINITY;
#pragma unroll
        for (int nt = 0; nt < 8; nt++) {
            mx = fmaxf(mx, fmaxf(fmaxf(sacc[nt][0], sacc[nt][1]),
                                 fmaxf(sacc[nt][2], sacc[nt][3])));
        }
#pragma unroll
        for (int d = 16; d >= 1; d >>= 1)
            mx = fmaxf(mx, __shfl_xor_sync(0xffffffffu, mx, d));

        if (mx > m) {                     // warp-uniform branch; rare after warmup
            const float sc = ex2f(m - mx);   // 0 on first tile
            m = mx;
#pragma unroll
            for (int nt = 0; nt < 4; nt++) {
                oacc[nt][0] *= sc; oacc[nt][1] *= sc;
                oacc[nt][2] *= sc; oacc[nt][3] *= sc;
            }
            lacc[0] *= sc; lacc[1] *= sc; lacc[2] *= sc; lacc[3] *= sc;
        }

        // ---- P = 2^(S - m) in f16 ----
        uint32_t hlo[8], hhi[8];
#pragma unroll
        for (int nt = 0; nt < 8; nt++) {
            __half2 d0 = __floats2half2_rn(sacc[nt][0] - m, sacc[nt][1] - m);
            __half2 d1 = __floats2half2_rn(sacc[nt][2] - m, sacc[nt][3] - m);
            hlo[nt] = h2ex2(*(uint32_t*)&d0);
            hhi[nt] = h2ex2(*(uint32_t*)&d1);
        }

        // ---- O += P V ; l += P @ 1 ----
#pragma unroll
        for (int kc = 0; kc < 4; kc++) {
            const uint32_t a0 = hlo[2 * kc];
            const uint32_t a1 = hhi[2 * kc];
            const uint32_t a2 = hlo[2 * kc + 1];
            const uint32_t a3 = hhi[2 * kc + 1];
            mma_f16(lacc[0], lacc[1], lacc[2], lacc[3],
                    a0, a1, a2, a3, ONES_F16X2, ONES_F16X2);
#pragma unroll
            for (int p = 0; p < 2; p++) {
                uint32_t b0, b1, b2, b3;
                const uint32_t addr = smem_u32(
                    &VsT[buf][p * 16 + rsel + ((quad >> 1) << 3)]
                             [kc * 16 + ((quad & 1) << 3)]);
                ldsm_x4(b0, b1, b2, b3, addr);
                mma_f16(oacc[2 * p][0], oacc[2 * p][1], oacc[2 * p][2], oacc[2 * p][3],
                        a0, a1, a2, a3, b0, b1);
                mma_f16(oacc[2 * p + 1][0], oacc[2 * p + 1][1], oacc[2 * p + 1][2], oacc[2 * p + 1][3],
                        a0, a1, a2, a3, b2, b3);
            }
        }

        // stage tile it+2 into buffer (it+2)%3
        if (it + 2 < NT) {
            stage((it + 2) * 64, (it + 2) % 3);
            cpa_commit();
        }
    }

    // ---- write partials (unnormalized) ----
    const int q0   = qt * 128 + w * 16 + g;
    const int row0 = bn * P2 + q0;
    const int row1 = row0 + 8;
    if (tig == 0) {
        g_pm[s][row0] = m;   g_pl[s][row0] = lacc[0];
        g_pm[s][row1] = m;   g_pl[s][row1] = lacc[2];
    }
    float* po0 = &g_po[s][(size_t)row0 * DV];
    float* po1 = &g_po[s][(size_t)row1 * DV];
#pragma unroll
    for (int nt = 0; nt < 4; nt++) {
        *(float2*)(po0 + nt * 8 + 2 * tig) = make_float2(oacc[nt][0], oacc[nt][1]);
        *(float2*)(po1 + nt * 8 + 2 * tig) = make_float2(oacc[nt][2], oacc[nt][3]);
    }
}

// ---------------------------------------------------------------------------
// Combine the four key-splits and normalize (8 elems/thread, float4).
// ---------------------------------------------------------------------------
__global__ __launch_bounds__(256)
void combine_kernel(float* __restrict__ out)
{
    const int idx = blockIdx.x * 256 + threadIdx.x;    // 131072 total
    const int row = idx >> 2;                          // bn*P2 + p
    const int d0  = (idx & 3) << 3;

    float pm[SPLIT];
#pragma unroll
    for (int s = 0; s < SPLIT; s++) pm[s] = g_pm[s][row];
    float M = pm[0];
#pragma unroll
    for (int s = 1; s < SPLIT; s++) M = fmaxf(M, pm[s]);

    float wgt[SPLIT];
    float den = 0.0f;
#pragma unroll
    for (int s = 0; s < SPLIT; s++) {
        wgt[s] = ex2f(pm[s] - M);
        den += g_pl[s][row] * wgt[s];
    }
    const float inv = 1.0f / den;
#pragma unroll
    for (int s = 0; s < SPLIT; s++) wgt[s] *= inv;

    const int b = row >> 13;
    const int n = (row >> 10) & 7;
    const int p = row & 1023;
    float4* o = (float4*)(out + ((size_t)(b * P2 + p) * 256) + n * DV + d0);

#pragma unroll
    for (int t = 0; t < 2; t++) {
        float4 r = make_float4(0.0f, 0.0f, 0.0f, 0.0f);
#pragma unroll
        for (int s = 0; s < SPLIT; s++) {
            float4 x = *(const float4*)&g_po[s][(size_t)row * DV + d0 + 4 * t];
            r.x += x.x * wgt[s];
            r.y += x.y * wgt[s];
            r.z += x.z * wgt[s];
            r.w += x.w * wgt[s];
        }
        o[t] = r;
    }
}

// ---------------------------------------------------------------------------
extern "C" void kernel_launch(void* const* d_in, const int* in_sizes, int n_in,
                              void* d_out, int out_size)
{
    const float* blob = (const float*)d_in[0];
    const float* wq   = (const float*)d_in[1];
    const float* bq   = (const float*)d_in[2];
    const float* wk   = (const float*)d_in[3];
    const float* bk   = (const float*)d_in[4];
    const float* wv   = (const float*)d_in[5];
    const float* bv   = (const float*)d_in[6];
    float* out        = (float*)d_out;

    prep_all<<<608, 256>>>(blob, wq, wk, wv);
    proj_gemm<<<576, 256>>>(bq, bk, bv);
    attn_tc_kernel<<<dim3(8, NH, BB * SPLIT), 256>>>();
    combine_kernel<<<512, 256>>>(out);
}